// round 14
// baseline (speedup 1.0000x reference)
#include <cuda_runtime.h>
#include <cuda_fp16.h>
#include <stdint.h>
#include <math.h>

#define NN 100000
#define EE 1600000
#define GG 64
#define SCAN_BLK 1024
#define NBLK_SCAN ((NN + SCAN_BLK - 1) / SCAN_BLK)   // 98

// ---------------- scratch (device globals; no allocation) ----------------
__device__ __align__(16) __half g_h1h[(size_t)NN * 256];  // x @ W1 (fp16)
__device__ __align__(16) __half g_e1h[(size_t)NN * 256];  // elu(aggregate1) (fp16)
__device__ __align__(16) __half g_h2h[(size_t)NN * 64];   // e1 @ W2 (fp16)
__device__ __align__(16) __half g_w1h[256 * 256];         // W1 fp16
__device__ __align__(16) __half g_w2h[256 * 64];          // W2 fp16
__device__ __align__(16) __half g_ew[(size_t)(EE + NN) * 4]; // per-edge softmax weights
__device__ __align__(16) __half g_o2h[(size_t)NN * 64];   // aggregate2 (fp16)
__device__ __align__(16) float g_asrc1[NN * 4];
__device__ __align__(16) float g_adst1[NN * 4];
__device__ float g_asrc2[NN];
__device__ float g_adst2[NN];
__device__ int   g_cnt[NN];
__device__ int   g_rowptr[NN + 1];
__device__ int   g_wpos[NN];
__device__ int   g_csr[EE + NN];
__device__ int   g_part[NBLK_SCAN + 8];
__device__ float g_emb[GG * 64];

// ---------------- helpers ----------------
__device__ __forceinline__ float lrelu(float a) { return a > 0.f ? a : 0.2f * a; }
__device__ __forceinline__ uint32_t smem_u32(const void* p) {
    return (uint32_t)__cvta_generic_to_shared(p);
}
__device__ __forceinline__ float warpMax(float v) {
    #pragma unroll
    for (int o = 16; o; o >>= 1) v = fmaxf(v, __shfl_xor_sync(0xffffffffu, v, o));
    return v;
}
__device__ __forceinline__ float warpSum(float v) {
    #pragma unroll
    for (int o = 16; o; o >>= 1) v += __shfl_xor_sync(0xffffffffu, v, o);
    return v;
}
__device__ __forceinline__ int warpSumI(int v) {
    #pragma unroll
    for (int o = 16; o; o >>= 1) v += __shfl_xor_sync(0xffffffffu, v, o);
    return v;
}
#define CP_ASYNC16(saddr, gptr) \
    asm volatile("cp.async.cg.shared.global [%0], [%1], 16;" :: "r"(saddr), "l"(gptr))
#define CP_COMMIT() asm volatile("cp.async.commit_group;")
#define CP_WAIT0()  asm volatile("cp.async.wait_group 0;")

// ---------------- prepW: convert W1/W2 to fp16 ----------------
__global__ void prepW(const float* __restrict__ W1, const float* __restrict__ W2) {
    int i = blockIdx.x * blockDim.x + threadIdx.x;
    if (i < 256 * 256) g_w1h[i] = __float2half_rn(W1[i]);
    if (i < 256 * 64)  g_w2h[i] = __float2half_rn(W2[i]);
}

// ---------------- FP16 tensor-core GEMM, double-buffered, cp.async --------
// ATT1: fuse 4-head attention dots (BN=128, Ncol=256, grid.x=2).
// ATT2: fuse 1-head attention dots (BN=64, Ncol=64, grid.x=1) -> g_asrc2/g_adst2.
#define APAD 8
#define BPAD 8
template <int BN, bool HALF_A, bool ATT1, bool ATT2>
__global__ __launch_bounds__(256)
void gemm_h(const void* __restrict__ Av, const __half* __restrict__ B,
            __half* __restrict__ C, int M, int K, int Ncol,
            const float* __restrict__ att_src, const float* __restrict__ att_dst) {
    const int BM = 128, BK = 32;
    const int NT = BN / 16;
    const int NB = BN / 32;
    __shared__ __half Ah[2][BM][BK + APAD];
    __shared__ __half Bs[2][BK][BN + BPAD];

    const int tid = threadIdx.x;
    const int warp = tid >> 5, lane = tid & 31;
    const int warpM = warp & 3, warpN = warp >> 2;
    const int rowBase = blockIdx.y * BM;
    const int colBase = blockIdx.x * BN;
    const int gid = lane >> 2;
    const int tig = lane & 3;

    float c[2][NT][4];
    #pragma unroll
    for (int mt = 0; mt < 2; mt++)
        #pragma unroll
        for (int nt = 0; nt < NT; nt++)
            #pragma unroll
            for (int r = 0; r < 4; r++) c[mt][nt][r] = 0.f;

    float4 raf[4];
    const int nk = K / BK;

    auto ldgA = [&](int kt) {
        if (!HALF_A) {
            const float* A = (const float*)Av;
            int k0 = kt * BK;
            #pragma unroll
            for (int it = 0; it < 4; it++) {
                int i = tid + it * 256;
                int r = i >> 3, q = i & 7;
                raf[it] = make_float4(0.f, 0.f, 0.f, 0.f);
                if (rowBase + r < M)
                    raf[it] = *(const float4*)(A + (size_t)(rowBase + r) * K + k0 + q * 4);
            }
        }
    };
    auto stsA = [&](int buf) {
        if (!HALF_A) {
            #pragma unroll
            for (int it = 0; it < 4; it++) {
                int i = tid + it * 256;
                int r = i >> 3, q = i & 7;
                __half2 h[2];
                h[0] = __floats2half2_rn(raf[it].x, raf[it].y);
                h[1] = __floats2half2_rn(raf[it].z, raf[it].w);
                *(uint2*)&Ah[buf][r][q * 4] = *(const uint2*)h;
            }
        }
    };
    auto asyncA = [&](int kt, int buf) {
        if (HALF_A) {
            const __half* A = (const __half*)Av;
            int k0 = kt * BK;
            #pragma unroll
            for (int it = 0; it < 2; it++) {
                int i = tid + it * 256;
                int r = i >> 2, q = i & 3;
                if (rowBase + r < M)
                    CP_ASYNC16(smem_u32(&Ah[buf][r][q * 8]),
                               A + (size_t)(rowBase + r) * K + k0 + q * 8);
            }
        }
    };
    auto asyncB = [&](int kt, int buf) {
        int k0 = kt * BK;
        #pragma unroll
        for (int it = 0; it < BN / 64; it++) {
            int i = tid + it * 256;
            int r = i / (BN / 8), q = i % (BN / 8);
            CP_ASYNC16(smem_u32(&Bs[buf][r][q * 8]),
                       B + (size_t)(k0 + r) * Ncol + colBase + q * 8);
        }
    };
    auto compute = [&](int buf) {
        #pragma unroll
        for (int ks = 0; ks < BK; ks += 16) {
            uint32_t a[2][4];
            #pragma unroll
            for (int mt = 0; mt < 2; mt++) {
                int lrow = warpM * 32 + mt * 16 + (lane & 15);
                int lcol = ks + ((lane >> 4) << 3);
                uint32_t addr = smem_u32(&Ah[buf][lrow][lcol]);
                asm volatile(
                    "ldmatrix.sync.aligned.m8n8.x4.shared.b16 {%0,%1,%2,%3}, [%4];"
                    : "=r"(a[mt][0]), "=r"(a[mt][1]), "=r"(a[mt][2]), "=r"(a[mt][3])
                    : "r"(addr));
            }
            uint32_t b[NT][2];
            #pragma unroll
            for (int hb = 0; hb < NB; hb++) {
                int krow = ks + (lane & 15);
                int ncol = warpN * (BN / 2) + hb * 16 + ((lane >> 4) << 3);
                uint32_t addr = smem_u32(&Bs[buf][krow][ncol]);
                uint32_t r0, r1, r2, r3;
                asm volatile(
                    "ldmatrix.sync.aligned.m8n8.x4.trans.shared.b16 {%0,%1,%2,%3}, [%4];"
                    : "=r"(r0), "=r"(r1), "=r"(r2), "=r"(r3)
                    : "r"(addr));
                b[hb * 2 + 0][0] = r0; b[hb * 2 + 0][1] = r1;
                b[hb * 2 + 1][0] = r2; b[hb * 2 + 1][1] = r3;
            }
            #pragma unroll
            for (int mt = 0; mt < 2; mt++)
                #pragma unroll
                for (int nt = 0; nt < NT; nt++) {
                    asm volatile(
                        "mma.sync.aligned.m16n8k16.row.col.f32.f16.f16.f32 "
                        "{%0,%1,%2,%3}, {%4,%5,%6,%7}, {%8,%9}, {%0,%1,%2,%3};"
                        : "+f"(c[mt][nt][0]), "+f"(c[mt][nt][1]),
                          "+f"(c[mt][nt][2]), "+f"(c[mt][nt][3])
                        : "r"(a[mt][0]), "r"(a[mt][1]), "r"(a[mt][2]), "r"(a[mt][3]),
                          "r"(b[nt][0]), "r"(b[nt][1]));
                }
        }
    };

    asyncB(0, 0); asyncA(0, 0); CP_COMMIT();
    ldgA(0); stsA(0);
    CP_WAIT0();
    __syncthreads();
    for (int kt = 0; kt < nk; kt++) {
        int buf = kt & 1;
        if (kt + 1 < nk) {
            asyncB(kt + 1, buf ^ 1);
            asyncA(kt + 1, buf ^ 1);
            CP_COMMIT();
            ldgA(kt + 1);
        }
        compute(buf);
        if (kt + 1 < nk) {
            stsA(buf ^ 1);
            CP_WAIT0();
            __syncthreads();
        }
    }

    #pragma unroll
    for (int mt = 0; mt < 2; mt++) {
        int row0 = rowBase + warpM * 32 + mt * 16 + gid;
        #pragma unroll
        for (int nt = 0; nt < NT; nt++) {
            int col = colBase + warpN * (BN / 2) + nt * 8 + tig * 2;
            if (row0 < M)
                *(__half2*)(C + (size_t)row0 * Ncol + col) =
                    __floats2half2_rn(c[mt][nt][0], c[mt][nt][1]);
            if (row0 + 8 < M)
                *(__half2*)(C + (size_t)(row0 + 8) * Ncol + col) =
                    __floats2half2_rn(c[mt][nt][2], c[mt][nt][3]);
        }
    }

    if (ATT1) {
        int head = blockIdx.x * 2 + warpN;
        const float* As_ = att_src + head * 64;
        const float* Ad_ = att_dst + head * 64;
        #pragma unroll
        for (int mt = 0; mt < 2; mt++) {
            float ps0 = 0.f, pd0 = 0.f, ps1 = 0.f, pd1 = 0.f;
            #pragma unroll
            for (int nt = 0; nt < NT; nt++) {
                int lc = nt * 8 + tig * 2;
                float w0 = As_[lc], w1 = As_[lc + 1];
                float v0 = Ad_[lc], v1 = Ad_[lc + 1];
                ps0 += c[mt][nt][0] * w0 + c[mt][nt][1] * w1;
                pd0 += c[mt][nt][0] * v0 + c[mt][nt][1] * v1;
                ps1 += c[mt][nt][2] * w0 + c[mt][nt][3] * w1;
                pd1 += c[mt][nt][2] * v0 + c[mt][nt][3] * v1;
            }
            #pragma unroll
            for (int o = 1; o < 4; o <<= 1) {
                ps0 += __shfl_xor_sync(0xffffffffu, ps0, o);
                pd0 += __shfl_xor_sync(0xffffffffu, pd0, o);
                ps1 += __shfl_xor_sync(0xffffffffu, ps1, o);
                pd1 += __shfl_xor_sync(0xffffffffu, pd1, o);
            }
            if (tig == 0) {
                int r0 = rowBase + warpM * 32 + mt * 16 + gid;
                if (r0 < M) {
                    g_asrc1[r0 * 4 + head] = ps0;
                    g_adst1[r0 * 4 + head] = pd0;
                }
                if (r0 + 8 < M) {
                    g_asrc1[(r0 + 8) * 4 + head] = ps1;
                    g_adst1[(r0 + 8) * 4 + head] = pd1;
                }
            }
        }
    }

    if (ATT2) {
        __shared__ float sps[2][BM], spd[2][BM];
        #pragma unroll
        for (int mt = 0; mt < 2; mt++) {
            float ps0 = 0.f, pd0 = 0.f, ps1 = 0.f, pd1 = 0.f;
            #pragma unroll
            for (int nt = 0; nt < NT; nt++) {
                int col = warpN * 32 + nt * 8 + tig * 2;
                float w0 = att_src[col], w1 = att_src[col + 1];
                float v0 = att_dst[col], v1 = att_dst[col + 1];
                ps0 += c[mt][nt][0] * w0 + c[mt][nt][1] * w1;
                pd0 += c[mt][nt][0] * v0 + c[mt][nt][1] * v1;
                ps1 += c[mt][nt][2] * w0 + c[mt][nt][3] * w1;
                pd1 += c[mt][nt][2] * v0 + c[mt][nt][3] * v1;
            }
            #pragma unroll
            for (int o = 1; o < 4; o <<= 1) {
                ps0 += __shfl_xor_sync(0xffffffffu, ps0, o);
                pd0 += __shfl_xor_sync(0xffffffffu, pd0, o);
                ps1 += __shfl_xor_sync(0xffffffffu, ps1, o);
                pd1 += __shfl_xor_sync(0xffffffffu, pd1, o);
            }
            if (tig == 0) {
                int lr = warpM * 32 + mt * 16 + gid;
                sps[warpN][lr] = ps0;  spd[warpN][lr] = pd0;
                sps[warpN][lr + 8] = ps1;  spd[warpN][lr + 8] = pd1;
            }
        }
        __syncthreads();
        if (tid < BM) {
            int r = rowBase + tid;
            if (r < M) {
                g_asrc2[r] = sps[0][tid] + sps[1][tid];
                g_adst2[r] = spd[0][tid] + spd[1][tid];
            }
        }
    }
}

// ---------------- CSR build ----------------
__global__ void init_cnt() {
    int i = blockIdx.x * blockDim.x + threadIdx.x;
    if (i < NN) g_cnt[i] = 1;  // self loop
}
__global__ void count_edges(const int* __restrict__ dst) {
    int e = blockIdx.x * blockDim.x + threadIdx.x;
    if (e < EE) atomicAdd(&g_cnt[dst[e]], 1);
}
__global__ void scan1() {
    __shared__ int wsum[32];
    int i = blockIdx.x * SCAN_BLK + threadIdx.x;
    int v = (i < NN) ? g_cnt[i] : 0;
    int lane = threadIdx.x & 31, wid = threadIdx.x >> 5;
    int incl = v;
    #pragma unroll
    for (int o = 1; o < 32; o <<= 1) {
        int t = __shfl_up_sync(0xffffffffu, incl, o);
        if (lane >= o) incl += t;
    }
    if (lane == 31) wsum[wid] = incl;
    __syncthreads();
    if (wid == 0) {
        int s = wsum[lane];
        #pragma unroll
        for (int o = 1; o < 32; o <<= 1) {
            int t = __shfl_up_sync(0xffffffffu, s, o);
            if (lane >= o) s += t;
        }
        wsum[lane] = s;
    }
    __syncthreads();
    int base = (wid > 0) ? wsum[wid - 1] : 0;
    incl += base;
    if (i < NN) g_rowptr[i] = incl - v;
    if (threadIdx.x == SCAN_BLK - 1) g_part[blockIdx.x] = incl;
}
// scan3: adds cross-chunk prefix computed in-block (replaces scan2 + scan3).
// FIXED: block-level base broadcast through shared memory (was warp-scope bug).
__global__ __launch_bounds__(256) void scan3() {
    __shared__ int red[8];
    __shared__ int s_base;
    int b = blockIdx.x;                    // 256-node block
    int part_idx = b >> 2;                 // SCAN_BLK=1024 => 4 blocks per chunk
    int t = threadIdx.x;
    // block-reduce sum of g_part[0 .. part_idx)
    int v = (t < part_idx) ? g_part[t] : 0;
    v = warpSumI(v);
    if ((t & 31) == 0) red[t >> 5] = v;
    __syncthreads();
    if (t < 32) {
        int s = (t < 8) ? red[t] : 0;
        #pragma unroll
        for (int o = 4; o; o >>= 1) s += __shfl_xor_sync(0xffffffffu, s, o);
        if (t == 0) s_base = s;
    }
    __syncthreads();
    int base = s_base;
    int i = b * 256 + t;
    if (i < NN) {
        int r = g_rowptr[i] + base;
        g_rowptr[i] = r;
        g_wpos[i] = r;
    }
    if (i == 0) g_rowptr[NN] = EE + NN;    // total is a compile-time constant
}
__global__ void scatter_edges(const int* __restrict__ src, const int* __restrict__ dst) {
    int e = blockIdx.x * blockDim.x + threadIdx.x;
    if (e < EE) {
        int d = dst[e];
        int pos = atomicAdd(&g_wpos[d], 1);
        g_csr[pos] = src[e];
    } else if (e < EE + NN) {
        int i = e - EE;
        int pos = atomicAdd(&g_wpos[i], 1);
        g_csr[pos] = i;
    }
}

// ---------------- layer-1 aggregation: warp per dst node ----------------
// Two-pass softmax stats; stored fp16 weights; depth-2 pipelined accumulate.
__global__ __launch_bounds__(256) void aggregate1(const float* __restrict__ b1) {
    int node = blockIdx.x * 8 + (threadIdx.x >> 5);
    if (node >= NN) return;
    int lane = threadIdx.x & 31;
    int beg = g_rowptr[node], end = g_rowptr[node + 1];
    float4 ad = *(const float4*)(g_adst1 + node * 4);

    float m0 = -1e30f, m1 = -1e30f, m2 = -1e30f, m3 = -1e30f;
    for (int e = beg + lane; e < end; e += 32) {
        int s = g_csr[e];
        float4 as = *(const float4*)(g_asrc1 + s * 4);
        m0 = fmaxf(m0, lrelu(as.x + ad.x));
        m1 = fmaxf(m1, lrelu(as.y + ad.y));
        m2 = fmaxf(m2, lrelu(as.z + ad.z));
        m3 = fmaxf(m3, lrelu(as.w + ad.w));
    }
    m0 = warpMax(m0); m1 = warpMax(m1); m2 = warpMax(m2); m3 = warpMax(m3);

    float s0 = 0.f, s1 = 0.f, s2 = 0.f, s3 = 0.f;
    for (int e = beg + lane; e < end; e += 32) {
        int s = g_csr[e];
        float4 as = *(const float4*)(g_asrc1 + s * 4);
        __half2 w01 = __floats2half2_rn(expf(lrelu(as.x + ad.x) - m0),
                                        expf(lrelu(as.y + ad.y) - m1));
        __half2 w23 = __floats2half2_rn(expf(lrelu(as.z + ad.z) - m2),
                                        expf(lrelu(as.w + ad.w) - m3));
        float2 f01 = __half22float2(w01);
        float2 f23 = __half22float2(w23);
        s0 += f01.x; s1 += f01.y; s2 += f23.x; s3 += f23.y;
        __half2 pk[2] = {w01, w23};
        *(uint2*)&g_ew[(size_t)e * 4] = *(const uint2*)pk;
    }
    s0 = warpSum(s0); s1 = warpSum(s1); s2 = warpSum(s2); s3 = warpSum(s3);
    float i0 = 1.f / (s0 + 1e-16f), i1 = 1.f / (s1 + 1e-16f);
    float i2 = 1.f / (s2 + 1e-16f), i3 = 1.f / (s3 + 1e-16f);

    int head = lane >> 3;
    float ih = head < 2 ? (head == 0 ? i0 : i1) : (head == 2 ? i2 : i3);

    float acc[8];
    #pragma unroll
    for (int k = 0; k < 8; k++) acc[k] = 0.f;

    const size_t loff = (size_t)lane * 8;
    __syncwarp();
    // depth-2 pipeline: stage (weight, row) for next edge while consuming current
    if (beg < end) {
        int s_cur = g_csr[beg];
        uint2 w_cur = *(const uint2*)&g_ew[(size_t)beg * 4];
        uint4 r_cur = *(const uint4*)(g_h1h + (size_t)s_cur * 256 + loff);
        for (int e = beg; e < end; ++e) {
            uint2 w_nxt; uint4 r_nxt;
            if (e + 1 < end) {
                int s_n = g_csr[e + 1];
                w_nxt = *(const uint2*)&g_ew[(size_t)(e + 1) * 4];
                r_nxt = *(const uint4*)(g_h1h + (size_t)s_n * 256 + loff);
            }
            const __half2* wp = (const __half2*)&w_cur;
            float2 f01 = __half22float2(wp[0]);
            float2 f23 = __half22float2(wp[1]);
            float w = (head < 2 ? (head == 0 ? f01.x : f01.y)
                                : (head == 2 ? f23.x : f23.y)) * ih;
            const __half2* hp = (const __half2*)&r_cur;
            #pragma unroll
            for (int q = 0; q < 4; q++) {
                float2 f = __half22float2(hp[q]);
                acc[q * 2]     = fmaf(w, f.x, acc[q * 2]);
                acc[q * 2 + 1] = fmaf(w, f.y, acc[q * 2 + 1]);
            }
            w_cur = w_nxt; r_cur = r_nxt;
        }
    }
    const float* bb = b1 + lane * 8;
    __half2 o[4];
    #pragma unroll
    for (int q = 0; q < 4; q++) {
        float r0 = acc[q * 2]     + bb[q * 2];
        float r1 = acc[q * 2 + 1] + bb[q * 2 + 1];
        r0 = r0 > 0.f ? r0 : (expf(r0) - 1.f);
        r1 = r1 > 0.f ? r1 : (expf(r1) - 1.f);
        o[q] = __floats2half2_rn(r0, r1);
    }
    *(uint4*)(g_e1h + (size_t)node * 256 + loff) = *(const uint4*)o;
}

// ---------------- layer-2 aggregation: stored weights + depth-2 pipeline ---
__global__ __launch_bounds__(256) void aggregate2(const float* __restrict__ b2) {
    int node = blockIdx.x * 8 + (threadIdx.x >> 5);
    if (node >= NN) return;
    int lane = threadIdx.x & 31;
    int beg = g_rowptr[node], end = g_rowptr[node + 1];
    float adv = g_adst2[node];

    float m = -1e30f;
    for (int e = beg + lane; e < end; e += 32)
        m = fmaxf(m, lrelu(g_asrc2[g_csr[e]] + adv));
    m = warpMax(m);
    float sm = 0.f;
    for (int e = beg + lane; e < end; e += 32) {
        __half wh = __float2half_rn(expf(lrelu(g_asrc2[g_csr[e]] + adv) - m));
        sm += __half2float(wh);
        g_ew[e] = wh;
    }
    sm = warpSum(sm);
    float inv = 1.f / (sm + 1e-16f);

    float a0 = 0.f, a1 = 0.f;
    const size_t loff = (size_t)lane * 2;
    __syncwarp();
    if (beg < end) {
        float w_cur = __half2float(g_ew[beg]);
        float2 v_cur = __half22float2(*(const __half2*)(g_h2h + (size_t)g_csr[beg] * 64 + loff));
        for (int e = beg; e < end; ++e) {
            float w_nxt = 0.f; float2 v_nxt = make_float2(0.f, 0.f);
            if (e + 1 < end) {
                w_nxt = __half2float(g_ew[e + 1]);
                v_nxt = __half22float2(*(const __half2*)(g_h2h + (size_t)g_csr[e + 1] * 64 + loff));
            }
            float w = w_cur * inv;
            a0 = fmaf(w, v_cur.x, a0);
            a1 = fmaf(w, v_cur.y, a1);
            w_cur = w_nxt; v_cur = v_nxt;
        }
    }
    *(__half2*)(g_o2h + (size_t)node * 64 + lane * 2) =
        __floats2half2_rn(a0 + b2[lane * 2], a1 + b2[lane * 2 + 1]);
}

// ---------------- global mean pool (batch is sorted) ----------------
__device__ __forceinline__ int lower_bound_i(const int* b, int n, int v) {
    int lo = 0, hi = n;
    while (lo < hi) {
        int mid = (lo + hi) >> 1;
        if (b[mid] < v) lo = mid + 1; else hi = mid;
    }
    return lo;
}
__global__ void pool(const int* __restrict__ batch) {
    __shared__ float part[256];
    __shared__ int sb, se;
    int g = blockIdx.x;
    if (threadIdx.x == 0) {
        sb = lower_bound_i(batch, NN, g);
        se = lower_bound_i(batch, NN, g + 1);
    }
    __syncthreads();
    int c = threadIdx.x & 63, q = threadIdx.x >> 6;
    float s = 0.f;
    for (int i = sb + q; i < se; i += 4)
        s += __half2float(g_o2h[(size_t)i * 64 + c]);
    part[threadIdx.x] = s;
    __syncthreads();
    if (q == 0) {
        float t = part[c] + part[c + 64] + part[c + 128] + part[c + 192];
        float cnt = (float)(se - sb);
        g_emb[g * 64 + c] = t / fmaxf(cnt, 1.f);
    }
}

// ---------------- final MLP ----------------
__global__ void mlp(const float* __restrict__ W3, const float* __restrict__ b3,
                    const float* __restrict__ W4, const float* __restrict__ b4,
                    float* __restrict__ out) {
    __shared__ float w3[64 * 32], w4[64], bb3[32], bb4[2];
    int t = threadIdx.x;
    for (int i = t; i < 2048; i += 64) w3[i] = W3[i];
    w4[t] = W4[t];
    if (t < 32) bb3[t] = b3[t];
    if (t < 2) bb4[t] = b4[t];
    __syncthreads();
    float e[64];
    #pragma unroll
    for (int k = 0; k < 64; k++) e[k] = g_emb[t * 64 + k];
    float l0 = bb4[0], l1 = bb4[1];
    #pragma unroll 4
    for (int j = 0; j < 32; j++) {
        float z = bb3[j];
        #pragma unroll
        for (int k = 0; k < 64; k++) z = fmaf(e[k], w3[k * 32 + j], z);
        z = fmaxf(z, 0.f);
        l0 = fmaf(z, w4[j * 2], l0);
        l1 = fmaf(z, w4[j * 2 + 1], l1);
    }
    out[t * 2] = l0;
    out[t * 2 + 1] = l1;
}

// ---------------- launch ----------------
extern "C" void kernel_launch(void* const* d_in, const int* in_sizes, int n_in,
                              void* d_out, int out_size) {
    const float* x = (const float*)d_in[0];
    const int* ei = (const int*)d_in[1];
    const int* batch = (const int*)d_in[2];
    const float* W1 = (const float*)d_in[3];
    const float* as1 = (const float*)d_in[4];
    const float* ad1 = (const float*)d_in[5];
    const float* b1 = (const float*)d_in[6];
    const float* W2 = (const float*)d_in[7];
    const float* as2 = (const float*)d_in[8];
    const float* ad2 = (const float*)d_in[9];
    const float* b2 = (const float*)d_in[10];
    const float* W3 = (const float*)d_in[11];
    const float* b3 = (const float*)d_in[12];
    const float* W4 = (const float*)d_in[13];
    const float* b4 = (const float*)d_in[14];
    float* out = (float*)d_out;

    const int* e_src = ei;
    const int* e_dst = ei + EE;

    void* p;
    cudaGetSymbolAddress(&p, g_h1h);  __half* h1 = (__half*)p;
    cudaGetSymbolAddress(&p, g_e1h);  __half* e1 = (__half*)p;
    cudaGetSymbolAddress(&p, g_h2h);  __half* h2 = (__half*)p;
    cudaGetSymbolAddress(&p, g_w1h);  __half* w1h = (__half*)p;
    cudaGetSymbolAddress(&p, g_w2h);  __half* w2h = (__half*)p;

    static cudaStream_t sB = nullptr;
    static cudaEvent_t evRoot = nullptr, evB = nullptr;
    if (!sB) {
        cudaStreamCreateWithFlags(&sB, cudaStreamNonBlocking);
        cudaEventCreateWithFlags(&evRoot, cudaEventDisableTiming);
        cudaEventCreateWithFlags(&evB, cudaEventDisableTiming);
    }

    const int agg_blocks = NN / 8;  // 12500, exact

    // ---- fork: CSR build on side stream, GEMM1(+att1) on main ----
    cudaEventRecord(evRoot, 0);
    cudaStreamWaitEvent(sB, evRoot, 0);

    prepW<<<256, 256>>>(W1, W2);
    init_cnt<<<(NN + 255) / 256, 256, 0, sB>>>();
    count_edges<<<(EE + 255) / 256, 256, 0, sB>>>(e_dst);
    gemm_h<128, false, true, false><<<dim3(2, 782), 256>>>(x, w1h, h1, NN, 256, 256, as1, ad1);
    scan1<<<NBLK_SCAN, SCAN_BLK, 0, sB>>>();
    scan3<<<(NN + 255) / 256, 256, 0, sB>>>();
    scatter_edges<<<(EE + NN + 255) / 256, 256, 0, sB>>>(e_src, e_dst);
    cudaEventRecord(evB, sB);
    cudaStreamWaitEvent(0, evB, 0);

    aggregate1<<<agg_blocks, 256>>>(b1);
    // GEMM2 with fused attn2 epilogue
    gemm_h<64, true, false, true><<<dim3(1, 782), 256>>>(e1, w2h, h2, NN, 256, 64, as2, ad2);
    aggregate2<<<agg_blocks, 256>>>(b2);
    pool<<<GG, 256>>>(batch);
    mlp<<<1, 64>>>(W3, b3, W4, b4, out);
}

// round 15
// speedup vs baseline: 1.1166x; 1.1166x over previous
#include <cuda_runtime.h>
#include <cuda_fp16.h>
#include <stdint.h>
#include <math.h>

#define NN 100000
#define EE 1600000
#define GG 64
#define SCAN_BLK 1024
#define NBLK_SCAN ((NN + SCAN_BLK - 1) / SCAN_BLK)   // 98

// ---------------- scratch (device globals; no allocation) ----------------
__device__ __align__(16) __half g_h1h[(size_t)NN * 256];  // x @ W1 (fp16)
__device__ __align__(16) __half g_e1h[(size_t)NN * 256];  // elu(aggregate1) (fp16)
__device__ __align__(16) __half g_h2h[(size_t)NN * 64];   // e1 @ W2 (fp16)
__device__ __align__(16) __half g_w1h[256 * 256];         // W1 fp16
__device__ __align__(16) __half g_w2h[256 * 64];          // W2 fp16
__device__ __align__(16) __half g_ew[(size_t)(EE + NN) * 4]; // per-edge softmax weights
__device__ __align__(16) __half g_o2h[(size_t)NN * 64];   // aggregate2 (fp16)
__device__ __align__(16) float g_asrc1[NN * 4];
__device__ __align__(16) float g_adst1[NN * 4];
__device__ float g_asrc2[NN];
__device__ float g_adst2[NN];
__device__ int   g_cnt[NN];
__device__ int   g_rowptr[NN + 1];
__device__ int   g_wpos[NN];
__device__ int   g_csr[EE + NN];
__device__ int   g_part[NBLK_SCAN + 8];
__device__ float g_emb[GG * 64];

// ---------------- helpers ----------------
__device__ __forceinline__ float lrelu(float a) { return a > 0.f ? a : 0.2f * a; }
__device__ __forceinline__ uint32_t smem_u32(const void* p) {
    return (uint32_t)__cvta_generic_to_shared(p);
}
__device__ __forceinline__ float warpMax(float v) {
    #pragma unroll
    for (int o = 16; o; o >>= 1) v = fmaxf(v, __shfl_xor_sync(0xffffffffu, v, o));
    return v;
}
__device__ __forceinline__ float warpSum(float v) {
    #pragma unroll
    for (int o = 16; o; o >>= 1) v += __shfl_xor_sync(0xffffffffu, v, o);
    return v;
}
__device__ __forceinline__ int warpSumI(int v) {
    #pragma unroll
    for (int o = 16; o; o >>= 1) v += __shfl_xor_sync(0xffffffffu, v, o);
    return v;
}
#define CP_ASYNC16(saddr, gptr) \
    asm volatile("cp.async.cg.shared.global [%0], [%1], 16;" :: "r"(saddr), "l"(gptr))
#define CP_COMMIT() asm volatile("cp.async.commit_group;")
#define CP_WAIT0()  asm volatile("cp.async.wait_group 0;")

// ---------------- prepW: convert W1/W2 to fp16 ----------------
__global__ void prepW(const float* __restrict__ W1, const float* __restrict__ W2) {
    int i = blockIdx.x * blockDim.x + threadIdx.x;
    if (i < 256 * 256) g_w1h[i] = __float2half_rn(W1[i]);
    if (i < 256 * 64)  g_w2h[i] = __float2half_rn(W2[i]);
}

// ---------------- FP16 tensor-core GEMM, double-buffered, cp.async --------
// ATT1: fuse 4-head attention dots (BN=128, Ncol=256, grid.x=2).
// ATT2: fuse 1-head attention dots (BN=64, Ncol=64, grid.x=1) -> g_asrc2/g_adst2.
#define APAD 8
#define BPAD 8
template <int BN, bool HALF_A, bool ATT1, bool ATT2>
__global__ __launch_bounds__(256)
void gemm_h(const void* __restrict__ Av, const __half* __restrict__ B,
            __half* __restrict__ C, int M, int K, int Ncol,
            const float* __restrict__ att_src, const float* __restrict__ att_dst) {
    const int BM = 128, BK = 32;
    const int NT = BN / 16;
    const int NB = BN / 32;
    __shared__ __half Ah[2][BM][BK + APAD];
    __shared__ __half Bs[2][BK][BN + BPAD];

    const int tid = threadIdx.x;
    const int warp = tid >> 5, lane = tid & 31;
    const int warpM = warp & 3, warpN = warp >> 2;
    const int rowBase = blockIdx.y * BM;
    const int colBase = blockIdx.x * BN;
    const int gid = lane >> 2;
    const int tig = lane & 3;

    float c[2][NT][4];
    #pragma unroll
    for (int mt = 0; mt < 2; mt++)
        #pragma unroll
        for (int nt = 0; nt < NT; nt++)
            #pragma unroll
            for (int r = 0; r < 4; r++) c[mt][nt][r] = 0.f;

    float4 raf[4];
    const int nk = K / BK;

    auto ldgA = [&](int kt) {
        if (!HALF_A) {
            const float* A = (const float*)Av;
            int k0 = kt * BK;
            #pragma unroll
            for (int it = 0; it < 4; it++) {
                int i = tid + it * 256;
                int r = i >> 3, q = i & 7;
                raf[it] = make_float4(0.f, 0.f, 0.f, 0.f);
                if (rowBase + r < M)
                    raf[it] = *(const float4*)(A + (size_t)(rowBase + r) * K + k0 + q * 4);
            }
        }
    };
    auto stsA = [&](int buf) {
        if (!HALF_A) {
            #pragma unroll
            for (int it = 0; it < 4; it++) {
                int i = tid + it * 256;
                int r = i >> 3, q = i & 7;
                __half2 h[2];
                h[0] = __floats2half2_rn(raf[it].x, raf[it].y);
                h[1] = __floats2half2_rn(raf[it].z, raf[it].w);
                *(uint2*)&Ah[buf][r][q * 4] = *(const uint2*)h;
            }
        }
    };
    auto asyncA = [&](int kt, int buf) {
        if (HALF_A) {
            const __half* A = (const __half*)Av;
            int k0 = kt * BK;
            #pragma unroll
            for (int it = 0; it < 2; it++) {
                int i = tid + it * 256;
                int r = i >> 2, q = i & 3;
                if (rowBase + r < M)
                    CP_ASYNC16(smem_u32(&Ah[buf][r][q * 8]),
                               A + (size_t)(rowBase + r) * K + k0 + q * 8);
            }
        }
    };
    auto asyncB = [&](int kt, int buf) {
        int k0 = kt * BK;
        #pragma unroll
        for (int it = 0; it < BN / 64; it++) {
            int i = tid + it * 256;
            int r = i / (BN / 8), q = i % (BN / 8);
            CP_ASYNC16(smem_u32(&Bs[buf][r][q * 8]),
                       B + (size_t)(k0 + r) * Ncol + colBase + q * 8);
        }
    };
    auto compute = [&](int buf) {
        #pragma unroll
        for (int ks = 0; ks < BK; ks += 16) {
            uint32_t a[2][4];
            #pragma unroll
            for (int mt = 0; mt < 2; mt++) {
                int lrow = warpM * 32 + mt * 16 + (lane & 15);
                int lcol = ks + ((lane >> 4) << 3);
                uint32_t addr = smem_u32(&Ah[buf][lrow][lcol]);
                asm volatile(
                    "ldmatrix.sync.aligned.m8n8.x4.shared.b16 {%0,%1,%2,%3}, [%4];"
                    : "=r"(a[mt][0]), "=r"(a[mt][1]), "=r"(a[mt][2]), "=r"(a[mt][3])
                    : "r"(addr));
            }
            uint32_t b[NT][2];
            #pragma unroll
            for (int hb = 0; hb < NB; hb++) {
                int krow = ks + (lane & 15);
                int ncol = warpN * (BN / 2) + hb * 16 + ((lane >> 4) << 3);
                uint32_t addr = smem_u32(&Bs[buf][krow][ncol]);
                uint32_t r0, r1, r2, r3;
                asm volatile(
                    "ldmatrix.sync.aligned.m8n8.x4.trans.shared.b16 {%0,%1,%2,%3}, [%4];"
                    : "=r"(r0), "=r"(r1), "=r"(r2), "=r"(r3)
                    : "r"(addr));
                b[hb * 2 + 0][0] = r0; b[hb * 2 + 0][1] = r1;
                b[hb * 2 + 1][0] = r2; b[hb * 2 + 1][1] = r3;
            }
            #pragma unroll
            for (int mt = 0; mt < 2; mt++)
                #pragma unroll
                for (int nt = 0; nt < NT; nt++) {
                    asm volatile(
                        "mma.sync.aligned.m16n8k16.row.col.f32.f16.f16.f32 "
                        "{%0,%1,%2,%3}, {%4,%5,%6,%7}, {%8,%9}, {%0,%1,%2,%3};"
                        : "+f"(c[mt][nt][0]), "+f"(c[mt][nt][1]),
                          "+f"(c[mt][nt][2]), "+f"(c[mt][nt][3])
                        : "r"(a[mt][0]), "r"(a[mt][1]), "r"(a[mt][2]), "r"(a[mt][3]),
                          "r"(b[nt][0]), "r"(b[nt][1]));
                }
        }
    };

    asyncB(0, 0); asyncA(0, 0); CP_COMMIT();
    ldgA(0); stsA(0);
    CP_WAIT0();
    __syncthreads();
    for (int kt = 0; kt < nk; kt++) {
        int buf = kt & 1;
        if (kt + 1 < nk) {
            asyncB(kt + 1, buf ^ 1);
            asyncA(kt + 1, buf ^ 1);
            CP_COMMIT();
            ldgA(kt + 1);
        }
        compute(buf);
        if (kt + 1 < nk) {
            stsA(buf ^ 1);
            CP_WAIT0();
            __syncthreads();
        }
    }

    #pragma unroll
    for (int mt = 0; mt < 2; mt++) {
        int row0 = rowBase + warpM * 32 + mt * 16 + gid;
        #pragma unroll
        for (int nt = 0; nt < NT; nt++) {
            int col = colBase + warpN * (BN / 2) + nt * 8 + tig * 2;
            if (row0 < M)
                *(__half2*)(C + (size_t)row0 * Ncol + col) =
                    __floats2half2_rn(c[mt][nt][0], c[mt][nt][1]);
            if (row0 + 8 < M)
                *(__half2*)(C + (size_t)(row0 + 8) * Ncol + col) =
                    __floats2half2_rn(c[mt][nt][2], c[mt][nt][3]);
        }
    }

    if (ATT1) {
        int head = blockIdx.x * 2 + warpN;
        const float* As_ = att_src + head * 64;
        const float* Ad_ = att_dst + head * 64;
        #pragma unroll
        for (int mt = 0; mt < 2; mt++) {
            float ps0 = 0.f, pd0 = 0.f, ps1 = 0.f, pd1 = 0.f;
            #pragma unroll
            for (int nt = 0; nt < NT; nt++) {
                int lc = nt * 8 + tig * 2;
                float w0 = As_[lc], w1 = As_[lc + 1];
                float v0 = Ad_[lc], v1 = Ad_[lc + 1];
                ps0 += c[mt][nt][0] * w0 + c[mt][nt][1] * w1;
                pd0 += c[mt][nt][0] * v0 + c[mt][nt][1] * v1;
                ps1 += c[mt][nt][2] * w0 + c[mt][nt][3] * w1;
                pd1 += c[mt][nt][2] * v0 + c[mt][nt][3] * v1;
            }
            #pragma unroll
            for (int o = 1; o < 4; o <<= 1) {
                ps0 += __shfl_xor_sync(0xffffffffu, ps0, o);
                pd0 += __shfl_xor_sync(0xffffffffu, pd0, o);
                ps1 += __shfl_xor_sync(0xffffffffu, ps1, o);
                pd1 += __shfl_xor_sync(0xffffffffu, pd1, o);
            }
            if (tig == 0) {
                int r0 = rowBase + warpM * 32 + mt * 16 + gid;
                if (r0 < M) {
                    g_asrc1[r0 * 4 + head] = ps0;
                    g_adst1[r0 * 4 + head] = pd0;
                }
                if (r0 + 8 < M) {
                    g_asrc1[(r0 + 8) * 4 + head] = ps1;
                    g_adst1[(r0 + 8) * 4 + head] = pd1;
                }
            }
        }
    }

    if (ATT2) {
        __shared__ float sps[2][BM], spd[2][BM];
        #pragma unroll
        for (int mt = 0; mt < 2; mt++) {
            float ps0 = 0.f, pd0 = 0.f, ps1 = 0.f, pd1 = 0.f;
            #pragma unroll
            for (int nt = 0; nt < NT; nt++) {
                int col = warpN * 32 + nt * 8 + tig * 2;
                float w0 = att_src[col], w1 = att_src[col + 1];
                float v0 = att_dst[col], v1 = att_dst[col + 1];
                ps0 += c[mt][nt][0] * w0 + c[mt][nt][1] * w1;
                pd0 += c[mt][nt][0] * v0 + c[mt][nt][1] * v1;
                ps1 += c[mt][nt][2] * w0 + c[mt][nt][3] * w1;
                pd1 += c[mt][nt][2] * v0 + c[mt][nt][3] * v1;
            }
            #pragma unroll
            for (int o = 1; o < 4; o <<= 1) {
                ps0 += __shfl_xor_sync(0xffffffffu, ps0, o);
                pd0 += __shfl_xor_sync(0xffffffffu, pd0, o);
                ps1 += __shfl_xor_sync(0xffffffffu, ps1, o);
                pd1 += __shfl_xor_sync(0xffffffffu, pd1, o);
            }
            if (tig == 0) {
                int lr = warpM * 32 + mt * 16 + gid;
                sps[warpN][lr] = ps0;  spd[warpN][lr] = pd0;
                sps[warpN][lr + 8] = ps1;  spd[warpN][lr + 8] = pd1;
            }
        }
        __syncthreads();
        if (tid < BM) {
            int r = rowBase + tid;
            if (r < M) {
                g_asrc2[r] = sps[0][tid] + sps[1][tid];
                g_adst2[r] = spd[0][tid] + spd[1][tid];
            }
        }
    }
}

// ---------------- CSR build ----------------
__global__ void init_cnt() {
    int i = blockIdx.x * blockDim.x + threadIdx.x;
    if (i < NN) g_cnt[i] = 1;  // self loop
}
__global__ void count_edges(const int* __restrict__ dst) {
    int e = blockIdx.x * blockDim.x + threadIdx.x;
    if (e < EE) atomicAdd(&g_cnt[dst[e]], 1);
}
__global__ void scan1() {
    __shared__ int wsum[32];
    int i = blockIdx.x * SCAN_BLK + threadIdx.x;
    int v = (i < NN) ? g_cnt[i] : 0;
    int lane = threadIdx.x & 31, wid = threadIdx.x >> 5;
    int incl = v;
    #pragma unroll
    for (int o = 1; o < 32; o <<= 1) {
        int t = __shfl_up_sync(0xffffffffu, incl, o);
        if (lane >= o) incl += t;
    }
    if (lane == 31) wsum[wid] = incl;
    __syncthreads();
    if (wid == 0) {
        int s = wsum[lane];
        #pragma unroll
        for (int o = 1; o < 32; o <<= 1) {
            int t = __shfl_up_sync(0xffffffffu, s, o);
            if (lane >= o) s += t;
        }
        wsum[lane] = s;
    }
    __syncthreads();
    int base = (wid > 0) ? wsum[wid - 1] : 0;
    incl += base;
    if (i < NN) g_rowptr[i] = incl - v;
    if (threadIdx.x == SCAN_BLK - 1) g_part[blockIdx.x] = incl;
}
// scan3: adds cross-chunk prefix computed in-block (replaces scan2 + scan3).
// Block-level base broadcast through shared memory.
__global__ __launch_bounds__(256) void scan3() {
    __shared__ int red[8];
    __shared__ int s_base;
    int b = blockIdx.x;                    // 256-node block
    int part_idx = b >> 2;                 // SCAN_BLK=1024 => 4 blocks per chunk
    int t = threadIdx.x;
    int v = (t < part_idx) ? g_part[t] : 0;
    v = warpSumI(v);
    if ((t & 31) == 0) red[t >> 5] = v;
    __syncthreads();
    if (t < 32) {
        int s = (t < 8) ? red[t] : 0;
        #pragma unroll
        for (int o = 4; o; o >>= 1) s += __shfl_xor_sync(0xffffffffu, s, o);
        if (t == 0) s_base = s;
    }
    __syncthreads();
    int base = s_base;
    int i = b * 256 + t;
    if (i < NN) {
        int r = g_rowptr[i] + base;
        g_rowptr[i] = r;
        g_wpos[i] = r;
    }
    if (i == 0) g_rowptr[NN] = EE + NN;
}
__global__ void scatter_edges(const int* __restrict__ src, const int* __restrict__ dst) {
    int e = blockIdx.x * blockDim.x + threadIdx.x;
    if (e < EE) {
        int d = dst[e];
        int pos = atomicAdd(&g_wpos[d], 1);
        g_csr[pos] = src[e];
    } else if (e < EE + NN) {
        int i = e - EE;
        int pos = atomicAdd(&g_wpos[i], 1);
        g_csr[pos] = i;
    }
}

// ---------------- layer-1 aggregation: warp per dst node ----------------
// Two-pass softmax stats; stored fp16 weights; PLAIN accumulate loop (R12 form).
__global__ __launch_bounds__(256) void aggregate1(const float* __restrict__ b1) {
    int node = blockIdx.x * 8 + (threadIdx.x >> 5);
    if (node >= NN) return;
    int lane = threadIdx.x & 31;
    int beg = g_rowptr[node], end = g_rowptr[node + 1];
    float4 ad = *(const float4*)(g_adst1 + node * 4);

    float m0 = -1e30f, m1 = -1e30f, m2 = -1e30f, m3 = -1e30f;
    for (int e = beg + lane; e < end; e += 32) {
        int s = g_csr[e];
        float4 as = *(const float4*)(g_asrc1 + s * 4);
        m0 = fmaxf(m0, lrelu(as.x + ad.x));
        m1 = fmaxf(m1, lrelu(as.y + ad.y));
        m2 = fmaxf(m2, lrelu(as.z + ad.z));
        m3 = fmaxf(m3, lrelu(as.w + ad.w));
    }
    m0 = warpMax(m0); m1 = warpMax(m1); m2 = warpMax(m2); m3 = warpMax(m3);

    float s0 = 0.f, s1 = 0.f, s2 = 0.f, s3 = 0.f;
    for (int e = beg + lane; e < end; e += 32) {
        int s = g_csr[e];
        float4 as = *(const float4*)(g_asrc1 + s * 4);
        __half2 w01 = __floats2half2_rn(expf(lrelu(as.x + ad.x) - m0),
                                        expf(lrelu(as.y + ad.y) - m1));
        __half2 w23 = __floats2half2_rn(expf(lrelu(as.z + ad.z) - m2),
                                        expf(lrelu(as.w + ad.w) - m3));
        float2 f01 = __half22float2(w01);
        float2 f23 = __half22float2(w23);
        s0 += f01.x; s1 += f01.y; s2 += f23.x; s3 += f23.y;
        __half2 pk[2] = {w01, w23};
        *(uint2*)&g_ew[(size_t)e * 4] = *(const uint2*)pk;
    }
    s0 = warpSum(s0); s1 = warpSum(s1); s2 = warpSum(s2); s3 = warpSum(s3);
    float i0 = 1.f / (s0 + 1e-16f), i1 = 1.f / (s1 + 1e-16f);
    float i2 = 1.f / (s2 + 1e-16f), i3 = 1.f / (s3 + 1e-16f);

    int head = lane >> 3;
    float ih = head < 2 ? (head == 0 ? i0 : i1) : (head == 2 ? i2 : i3);

    float acc[8];
    #pragma unroll
    for (int k = 0; k < 8; k++) acc[k] = 0.f;

    const size_t loff = (size_t)lane * 8;
    __syncwarp();
    for (int e = beg; e < end; ++e) {
        int s = g_csr[e];
        uint2 wraw = *(const uint2*)&g_ew[(size_t)e * 4];   // broadcast
        const __half2* wp = (const __half2*)&wraw;
        float2 f01 = __half22float2(wp[0]);
        float2 f23 = __half22float2(wp[1]);
        float w = (head < 2 ? (head == 0 ? f01.x : f01.y)
                            : (head == 2 ? f23.x : f23.y)) * ih;
        uint4 raw = *(const uint4*)(g_h1h + (size_t)s * 256 + loff);
        const __half2* hp = (const __half2*)&raw;
        #pragma unroll
        for (int q = 0; q < 4; q++) {
            float2 f = __half22float2(hp[q]);
            acc[q * 2]     = fmaf(w, f.x, acc[q * 2]);
            acc[q * 2 + 1] = fmaf(w, f.y, acc[q * 2 + 1]);
        }
    }
    const float* bb = b1 + lane * 8;
    __half2 o[4];
    #pragma unroll
    for (int q = 0; q < 4; q++) {
        float r0 = acc[q * 2]     + bb[q * 2];
        float r1 = acc[q * 2 + 1] + bb[q * 2 + 1];
        r0 = r0 > 0.f ? r0 : (expf(r0) - 1.f);
        r1 = r1 > 0.f ? r1 : (expf(r1) - 1.f);
        o[q] = __floats2half2_rn(r0, r1);
    }
    *(uint4*)(g_e1h + (size_t)node * 256 + loff) = *(const uint4*)o;
}

// ---------------- layer-2 aggregation: stored weights, plain loop ---------
__global__ __launch_bounds__(256) void aggregate2(const float* __restrict__ b2) {
    int node = blockIdx.x * 8 + (threadIdx.x >> 5);
    if (node >= NN) return;
    int lane = threadIdx.x & 31;
    int beg = g_rowptr[node], end = g_rowptr[node + 1];
    float adv = g_adst2[node];

    float m = -1e30f;
    for (int e = beg + lane; e < end; e += 32)
        m = fmaxf(m, lrelu(g_asrc2[g_csr[e]] + adv));
    m = warpMax(m);
    float sm = 0.f;
    for (int e = beg + lane; e < end; e += 32) {
        __half wh = __float2half_rn(expf(lrelu(g_asrc2[g_csr[e]] + adv) - m));
        sm += __half2float(wh);
        g_ew[e] = wh;
    }
    sm = warpSum(sm);
    float inv = 1.f / (sm + 1e-16f);

    float a0 = 0.f, a1 = 0.f;
    const size_t loff = (size_t)lane * 2;
    __syncwarp();
    for (int e = beg; e < end; ++e) {
        int s = g_csr[e];
        float w = __half2float(g_ew[e]) * inv;   // broadcast
        float2 v = __half22float2(*(const __half2*)(g_h2h + (size_t)s * 64 + loff));
        a0 = fmaf(w, v.x, a0);
        a1 = fmaf(w, v.y, a1);
    }
    *(__half2*)(g_o2h + (size_t)node * 64 + lane * 2) =
        __floats2half2_rn(a0 + b2[lane * 2], a1 + b2[lane * 2 + 1]);
}

// ---------------- global mean pool (batch is sorted) ----------------
__device__ __forceinline__ int lower_bound_i(const int* b, int n, int v) {
    int lo = 0, hi = n;
    while (lo < hi) {
        int mid = (lo + hi) >> 1;
        if (b[mid] < v) lo = mid + 1; else hi = mid;
    }
    return lo;
}
__global__ void pool(const int* __restrict__ batch) {
    __shared__ float part[256];
    __shared__ int sb, se;
    int g = blockIdx.x;
    if (threadIdx.x == 0) {
        sb = lower_bound_i(batch, NN, g);
        se = lower_bound_i(batch, NN, g + 1);
    }
    __syncthreads();
    int c = threadIdx.x & 63, q = threadIdx.x >> 6;
    float s = 0.f;
    for (int i = sb + q; i < se; i += 4)
        s += __half2float(g_o2h[(size_t)i * 64 + c]);
    part[threadIdx.x] = s;
    __syncthreads();
    if (q == 0) {
        float t = part[c] + part[c + 64] + part[c + 128] + part[c + 192];
        float cnt = (float)(se - sb);
        g_emb[g * 64 + c] = t / fmaxf(cnt, 1.f);
    }
}

// ---------------- final MLP ----------------
__global__ void mlp(const float* __restrict__ W3, const float* __restrict__ b3,
                    const float* __restrict__ W4, const float* __restrict__ b4,
                    float* __restrict__ out) {
    __shared__ float w3[64 * 32], w4[64], bb3[32], bb4[2];
    int t = threadIdx.x;
    for (int i = t; i < 2048; i += 64) w3[i] = W3[i];
    w4[t] = W4[t];
    if (t < 32) bb3[t] = b3[t];
    if (t < 2) bb4[t] = b4[t];
    __syncthreads();
    float e[64];
    #pragma unroll
    for (int k = 0; k < 64; k++) e[k] = g_emb[t * 64 + k];
    float l0 = bb4[0], l1 = bb4[1];
    #pragma unroll 4
    for (int j = 0; j < 32; j++) {
        float z = bb3[j];
        #pragma unroll
        for (int k = 0; k < 64; k++) z = fmaf(e[k], w3[k * 32 + j], z);
        z = fmaxf(z, 0.f);
        l0 = fmaf(z, w4[j * 2], l0);
        l1 = fmaf(z, w4[j * 2 + 1], l1);
    }
    out[t * 2] = l0;
    out[t * 2 + 1] = l1;
}

// ---------------- launch ----------------
extern "C" void kernel_launch(void* const* d_in, const int* in_sizes, int n_in,
                              void* d_out, int out_size) {
    const float* x = (const float*)d_in[0];
    const int* ei = (const int*)d_in[1];
    const int* batch = (const int*)d_in[2];
    const float* W1 = (const float*)d_in[3];
    const float* as1 = (const float*)d_in[4];
    const float* ad1 = (const float*)d_in[5];
    const float* b1 = (const float*)d_in[6];
    const float* W2 = (const float*)d_in[7];
    const float* as2 = (const float*)d_in[8];
    const float* ad2 = (const float*)d_in[9];
    const float* b2 = (const float*)d_in[10];
    const float* W3 = (const float*)d_in[11];
    const float* b3 = (const float*)d_in[12];
    const float* W4 = (const float*)d_in[13];
    const float* b4 = (const float*)d_in[14];
    float* out = (float*)d_out;

    const int* e_src = ei;
    const int* e_dst = ei + EE;

    void* p;
    cudaGetSymbolAddress(&p, g_h1h);  __half* h1 = (__half*)p;
    cudaGetSymbolAddress(&p, g_e1h);  __half* e1 = (__half*)p;
    cudaGetSymbolAddress(&p, g_h2h);  __half* h2 = (__half*)p;
    cudaGetSymbolAddress(&p, g_w1h);  __half* w1h = (__half*)p;
    cudaGetSymbolAddress(&p, g_w2h);  __half* w2h = (__half*)p;

    static cudaStream_t sB = nullptr;
    static cudaEvent_t evRoot = nullptr, evB = nullptr;
    if (!sB) {
        cudaStreamCreateWithFlags(&sB, cudaStreamNonBlocking);
        cudaEventCreateWithFlags(&evRoot, cudaEventDisableTiming);
        cudaEventCreateWithFlags(&evB, cudaEventDisableTiming);
    }

    const int agg_blocks = NN / 8;  // 12500, exact

    // ---- fork: CSR build on side stream, GEMM1(+att1) on main ----
    cudaEventRecord(evRoot, 0);
    cudaStreamWaitEvent(sB, evRoot, 0);

    prepW<<<256, 256>>>(W1, W2);
    init_cnt<<<(NN + 255) / 256, 256, 0, sB>>>();
    count_edges<<<(EE + 255) / 256, 256, 0, sB>>>(e_dst);
    gemm_h<128, false, true, false><<<dim3(2, 782), 256>>>(x, w1h, h1, NN, 256, 256, as1, ad1);
    scan1<<<NBLK_SCAN, SCAN_BLK, 0, sB>>>();
    scan3<<<(NN + 255) / 256, 256, 0, sB>>>();
    scatter_edges<<<(EE + NN + 255) / 256, 256, 0, sB>>>(e_src, e_dst);
    cudaEventRecord(evB, sB);
    cudaStreamWaitEvent(0, evB, 0);

    aggregate1<<<agg_blocks, 256>>>(b1);
    // GEMM2 with fused attn2 epilogue
    gemm_h<64, true, false, true><<<dim3(1, 782), 256>>>(e1, w2h, h2, NN, 256, 64, as2, ad2);
    aggregate2<<<agg_blocks, 256>>>(b2);
    pool<<<GG, 256>>>(batch);
    mlp<<<1, 64>>>(W3, b3, W4, b4, out);
}

// round 16
// speedup vs baseline: 1.2085x; 1.0823x over previous
#include <cuda_runtime.h>
#include <cuda_fp16.h>
#include <stdint.h>
#include <math.h>

#define NN 100000
#define EE 1600000
#define GG 64
#define SCAN_BLK 1024
#define NBLK_SCAN ((NN + SCAN_BLK - 1) / SCAN_BLK)   // 98

// ---------------- scratch (device globals; no allocation) ----------------
__device__ __align__(16) __half g_h1h[(size_t)NN * 256];  // x @ W1 (fp16)
__device__ __align__(16) __half g_e1h[(size_t)NN * 256];  // elu(aggregate1) (fp16)
__device__ __align__(16) __half g_h2h[(size_t)NN * 64];   // e1 @ W2 (fp16)
__device__ __align__(16) __half g_w1h[256 * 256];         // W1 fp16
__device__ __align__(16) __half g_w2h[256 * 64];          // W2 fp16
__device__ __align__(16) float g_ewf[(size_t)(EE + NN) * 4]; // per-edge weights (fp32)
__device__ __align__(16) __half g_o2h[(size_t)NN * 64];   // aggregate2 (fp16)
__device__ __align__(16) float g_asrc1[NN * 4];
__device__ __align__(16) float g_adst1[NN * 4];
__device__ float g_asrc2[NN];
__device__ float g_adst2[NN];
__device__ int   g_cnt[NN];
__device__ int   g_rowptr[NN + 1];
__device__ int   g_wpos[NN];
__device__ int   g_csr[EE + NN];
__device__ int   g_part[NBLK_SCAN + 8];
__device__ float g_emb[GG * 64];
__device__ int   g_poolctr;

// ---------------- helpers ----------------
__device__ __forceinline__ float lrelu(float a) { return a > 0.f ? a : 0.2f * a; }
__device__ __forceinline__ uint32_t smem_u32(const void* p) {
    return (uint32_t)__cvta_generic_to_shared(p);
}
__device__ __forceinline__ float warpSum(float v) {
    #pragma unroll
    for (int o = 16; o; o >>= 1) v += __shfl_xor_sync(0xffffffffu, v, o);
    return v;
}
__device__ __forceinline__ int warpSumI(int v) {
    #pragma unroll
    for (int o = 16; o; o >>= 1) v += __shfl_xor_sync(0xffffffffu, v, o);
    return v;
}
#define CP_ASYNC16(saddr, gptr) \
    asm volatile("cp.async.cg.shared.global [%0], [%1], 16;" :: "r"(saddr), "l"(gptr))
#define CP_COMMIT() asm volatile("cp.async.commit_group;")
#define CP_WAIT0()  asm volatile("cp.async.wait_group 0;")

// ---------------- prepW: convert W1/W2 to fp16 ----------------
__global__ void prepW(const float* __restrict__ W1, const float* __restrict__ W2) {
    int i = blockIdx.x * blockDim.x + threadIdx.x;
    if (i < 256 * 256) g_w1h[i] = __float2half_rn(W1[i]);
    if (i < 256 * 64)  g_w2h[i] = __float2half_rn(W2[i]);
}

// ---------------- FP16 tensor-core GEMM, double-buffered, cp.async --------
// ATT1: fuse 4-head attention dots (BN=128, Ncol=256, grid.x=2).
// ATT2: fuse 1-head attention dots (BN=64, Ncol=64, grid.x=1) -> g_asrc2/g_adst2.
#define APAD 8
#define BPAD 8
template <int BN, bool HALF_A, bool ATT1, bool ATT2>
__global__ __launch_bounds__(256)
void gemm_h(const void* __restrict__ Av, const __half* __restrict__ B,
            __half* __restrict__ C, int M, int K, int Ncol,
            const float* __restrict__ att_src, const float* __restrict__ att_dst) {
    const int BM = 128, BK = 32;
    const int NT = BN / 16;
    const int NB = BN / 32;
    __shared__ __half Ah[2][BM][BK + APAD];
    __shared__ __half Bs[2][BK][BN + BPAD];

    const int tid = threadIdx.x;
    const int warp = tid >> 5, lane = tid & 31;
    const int warpM = warp & 3, warpN = warp >> 2;
    const int rowBase = blockIdx.y * BM;
    const int colBase = blockIdx.x * BN;
    const int gid = lane >> 2;
    const int tig = lane & 3;

    float c[2][NT][4];
    #pragma unroll
    for (int mt = 0; mt < 2; mt++)
        #pragma unroll
        for (int nt = 0; nt < NT; nt++)
            #pragma unroll
            for (int r = 0; r < 4; r++) c[mt][nt][r] = 0.f;

    float4 raf[4];
    const int nk = K / BK;

    auto ldgA = [&](int kt) {
        if (!HALF_A) {
            const float* A = (const float*)Av;
            int k0 = kt * BK;
            #pragma unroll
            for (int it = 0; it < 4; it++) {
                int i = tid + it * 256;
                int r = i >> 3, q = i & 7;
                raf[it] = make_float4(0.f, 0.f, 0.f, 0.f);
                if (rowBase + r < M)
                    raf[it] = *(const float4*)(A + (size_t)(rowBase + r) * K + k0 + q * 4);
            }
        }
    };
    auto stsA = [&](int buf) {
        if (!HALF_A) {
            #pragma unroll
            for (int it = 0; it < 4; it++) {
                int i = tid + it * 256;
                int r = i >> 3, q = i & 7;
                __half2 h[2];
                h[0] = __floats2half2_rn(raf[it].x, raf[it].y);
                h[1] = __floats2half2_rn(raf[it].z, raf[it].w);
                *(uint2*)&Ah[buf][r][q * 4] = *(const uint2*)h;
            }
        }
    };
    auto asyncA = [&](int kt, int buf) {
        if (HALF_A) {
            const __half* A = (const __half*)Av;
            int k0 = kt * BK;
            #pragma unroll
            for (int it = 0; it < 2; it++) {
                int i = tid + it * 256;
                int r = i >> 2, q = i & 3;
                if (rowBase + r < M)
                    CP_ASYNC16(smem_u32(&Ah[buf][r][q * 8]),
                               A + (size_t)(rowBase + r) * K + k0 + q * 8);
            }
        }
    };
    auto asyncB = [&](int kt, int buf) {
        int k0 = kt * BK;
        #pragma unroll
        for (int it = 0; it < BN / 64; it++) {
            int i = tid + it * 256;
            int r = i / (BN / 8), q = i % (BN / 8);
            CP_ASYNC16(smem_u32(&Bs[buf][r][q * 8]),
                       B + (size_t)(k0 + r) * Ncol + colBase + q * 8);
        }
    };
    auto compute = [&](int buf) {
        #pragma unroll
        for (int ks = 0; ks < BK; ks += 16) {
            uint32_t a[2][4];
            #pragma unroll
            for (int mt = 0; mt < 2; mt++) {
                int lrow = warpM * 32 + mt * 16 + (lane & 15);
                int lcol = ks + ((lane >> 4) << 3);
                uint32_t addr = smem_u32(&Ah[buf][lrow][lcol]);
                asm volatile(
                    "ldmatrix.sync.aligned.m8n8.x4.shared.b16 {%0,%1,%2,%3}, [%4];"
                    : "=r"(a[mt][0]), "=r"(a[mt][1]), "=r"(a[mt][2]), "=r"(a[mt][3])
                    : "r"(addr));
            }
            uint32_t b[NT][2];
            #pragma unroll
            for (int hb = 0; hb < NB; hb++) {
                int krow = ks + (lane & 15);
                int ncol = warpN * (BN / 2) + hb * 16 + ((lane >> 4) << 3);
                uint32_t addr = smem_u32(&Bs[buf][krow][ncol]);
                uint32_t r0, r1, r2, r3;
                asm volatile(
                    "ldmatrix.sync.aligned.m8n8.x4.trans.shared.b16 {%0,%1,%2,%3}, [%4];"
                    : "=r"(r0), "=r"(r1), "=r"(r2), "=r"(r3)
                    : "r"(addr));
                b[hb * 2 + 0][0] = r0; b[hb * 2 + 0][1] = r1;
                b[hb * 2 + 1][0] = r2; b[hb * 2 + 1][1] = r3;
            }
            #pragma unroll
            for (int mt = 0; mt < 2; mt++)
                #pragma unroll
                for (int nt = 0; nt < NT; nt++) {
                    asm volatile(
                        "mma.sync.aligned.m16n8k16.row.col.f32.f16.f16.f32 "
                        "{%0,%1,%2,%3}, {%4,%5,%6,%7}, {%8,%9}, {%0,%1,%2,%3};"
                        : "+f"(c[mt][nt][0]), "+f"(c[mt][nt][1]),
                          "+f"(c[mt][nt][2]), "+f"(c[mt][nt][3])
                        : "r"(a[mt][0]), "r"(a[mt][1]), "r"(a[mt][2]), "r"(a[mt][3]),
                          "r"(b[nt][0]), "r"(b[nt][1]));
                }
        }
    };

    asyncB(0, 0); asyncA(0, 0); CP_COMMIT();
    ldgA(0); stsA(0);
    CP_WAIT0();
    __syncthreads();
    for (int kt = 0; kt < nk; kt++) {
        int buf = kt & 1;
        if (kt + 1 < nk) {
            asyncB(kt + 1, buf ^ 1);
            asyncA(kt + 1, buf ^ 1);
            CP_COMMIT();
            ldgA(kt + 1);
        }
        compute(buf);
        if (kt + 1 < nk) {
            stsA(buf ^ 1);
            CP_WAIT0();
            __syncthreads();
        }
    }

    #pragma unroll
    for (int mt = 0; mt < 2; mt++) {
        int row0 = rowBase + warpM * 32 + mt * 16 + gid;
        #pragma unroll
        for (int nt = 0; nt < NT; nt++) {
            int col = colBase + warpN * (BN / 2) + nt * 8 + tig * 2;
            if (row0 < M)
                *(__half2*)(C + (size_t)row0 * Ncol + col) =
                    __floats2half2_rn(c[mt][nt][0], c[mt][nt][1]);
            if (row0 + 8 < M)
                *(__half2*)(C + (size_t)(row0 + 8) * Ncol + col) =
                    __floats2half2_rn(c[mt][nt][2], c[mt][nt][3]);
        }
    }

    if (ATT1) {
        int head = blockIdx.x * 2 + warpN;
        const float* As_ = att_src + head * 64;
        const float* Ad_ = att_dst + head * 64;
        #pragma unroll
        for (int mt = 0; mt < 2; mt++) {
            float ps0 = 0.f, pd0 = 0.f, ps1 = 0.f, pd1 = 0.f;
            #pragma unroll
            for (int nt = 0; nt < NT; nt++) {
                int lc = nt * 8 + tig * 2;
                float w0 = As_[lc], w1 = As_[lc + 1];
                float v0 = Ad_[lc], v1 = Ad_[lc + 1];
                ps0 += c[mt][nt][0] * w0 + c[mt][nt][1] * w1;
                pd0 += c[mt][nt][0] * v0 + c[mt][nt][1] * v1;
                ps1 += c[mt][nt][2] * w0 + c[mt][nt][3] * w1;
                pd1 += c[mt][nt][2] * v0 + c[mt][nt][3] * v1;
            }
            #pragma unroll
            for (int o = 1; o < 4; o <<= 1) {
                ps0 += __shfl_xor_sync(0xffffffffu, ps0, o);
                pd0 += __shfl_xor_sync(0xffffffffu, pd0, o);
                ps1 += __shfl_xor_sync(0xffffffffu, ps1, o);
                pd1 += __shfl_xor_sync(0xffffffffu, pd1, o);
            }
            if (tig == 0) {
                int r0 = rowBase + warpM * 32 + mt * 16 + gid;
                if (r0 < M) {
                    g_asrc1[r0 * 4 + head] = ps0;
                    g_adst1[r0 * 4 + head] = pd0;
                }
                if (r0 + 8 < M) {
                    g_asrc1[(r0 + 8) * 4 + head] = ps1;
                    g_adst1[(r0 + 8) * 4 + head] = pd1;
                }
            }
        }
    }

    if (ATT2) {
        __shared__ float sps[2][BM], spd[2][BM];
        #pragma unroll
        for (int mt = 0; mt < 2; mt++) {
            float ps0 = 0.f, pd0 = 0.f, ps1 = 0.f, pd1 = 0.f;
            #pragma unroll
            for (int nt = 0; nt < NT; nt++) {
                int col = warpN * 32 + nt * 8 + tig * 2;
                float w0 = att_src[col], w1 = att_src[col + 1];
                float v0 = att_dst[col], v1 = att_dst[col + 1];
                ps0 += c[mt][nt][0] * w0 + c[mt][nt][1] * w1;
                pd0 += c[mt][nt][0] * v0 + c[mt][nt][1] * v1;
                ps1 += c[mt][nt][2] * w0 + c[mt][nt][3] * w1;
                pd1 += c[mt][nt][2] * v0 + c[mt][nt][3] * v1;
            }
            #pragma unroll
            for (int o = 1; o < 4; o <<= 1) {
                ps0 += __shfl_xor_sync(0xffffffffu, ps0, o);
                pd0 += __shfl_xor_sync(0xffffffffu, pd0, o);
                ps1 += __shfl_xor_sync(0xffffffffu, ps1, o);
                pd1 += __shfl_xor_sync(0xffffffffu, pd1, o);
            }
            if (tig == 0) {
                int lr = warpM * 32 + mt * 16 + gid;
                sps[warpN][lr] = ps0;  spd[warpN][lr] = pd0;
                sps[warpN][lr + 8] = ps1;  spd[warpN][lr + 8] = pd1;
            }
        }
        __syncthreads();
        if (tid < BM) {
            int r = rowBase + tid;
            if (r < M) {
                g_asrc2[r] = sps[0][tid] + sps[1][tid];
                g_adst2[r] = spd[0][tid] + spd[1][tid];
            }
        }
    }
}

// ---------------- CSR build ----------------
__global__ void init_cnt() {
    int i = blockIdx.x * blockDim.x + threadIdx.x;
    if (i < NN) g_cnt[i] = 1;  // self loop
}
__global__ void count_edges(const int* __restrict__ dst) {
    int e = blockIdx.x * blockDim.x + threadIdx.x;
    if (e < EE) atomicAdd(&g_cnt[dst[e]], 1);
}
__global__ void scan1() {
    __shared__ int wsum[32];
    int i = blockIdx.x * SCAN_BLK + threadIdx.x;
    int v = (i < NN) ? g_cnt[i] : 0;
    int lane = threadIdx.x & 31, wid = threadIdx.x >> 5;
    int incl = v;
    #pragma unroll
    for (int o = 1; o < 32; o <<= 1) {
        int t = __shfl_up_sync(0xffffffffu, incl, o);
        if (lane >= o) incl += t;
    }
    if (lane == 31) wsum[wid] = incl;
    __syncthreads();
    if (wid == 0) {
        int s = wsum[lane];
        #pragma unroll
        for (int o = 1; o < 32; o <<= 1) {
            int t = __shfl_up_sync(0xffffffffu, s, o);
            if (lane >= o) s += t;
        }
        wsum[lane] = s;
    }
    __syncthreads();
    int base = (wid > 0) ? wsum[wid - 1] : 0;
    incl += base;
    if (i < NN) g_rowptr[i] = incl - v;
    if (threadIdx.x == SCAN_BLK - 1) g_part[blockIdx.x] = incl;
}
// scan3: adds cross-chunk prefix computed in-block (replaces scan2 + scan3).
__global__ __launch_bounds__(256) void scan3() {
    __shared__ int red[8];
    __shared__ int s_base;
    int b = blockIdx.x;
    int part_idx = b >> 2;
    int t = threadIdx.x;
    int v = (t < part_idx) ? g_part[t] : 0;
    v = warpSumI(v);
    if ((t & 31) == 0) red[t >> 5] = v;
    __syncthreads();
    if (t < 32) {
        int s = (t < 8) ? red[t] : 0;
        #pragma unroll
        for (int o = 4; o; o >>= 1) s += __shfl_xor_sync(0xffffffffu, s, o);
        if (t == 0) s_base = s;
    }
    __syncthreads();
    int base = s_base;
    int i = b * 256 + t;
    if (i < NN) {
        int r = g_rowptr[i] + base;
        g_rowptr[i] = r;
        g_wpos[i] = r;
    }
    if (i == 0) g_rowptr[NN] = EE + NN;
}
__global__ void scatter_edges(const int* __restrict__ src, const int* __restrict__ dst) {
    int e = blockIdx.x * blockDim.x + threadIdx.x;
    if (e < EE) {
        int d = dst[e];
        int pos = atomicAdd(&g_wpos[d], 1);
        g_csr[pos] = src[e];
    } else if (e < EE + NN) {
        int i = e - EE;
        int pos = atomicAdd(&g_wpos[i], 1);
        g_csr[pos] = i;
    }
}

// ---------------- layer-1 aggregation: warp per dst node ----------------
// Single stats pass (no max subtraction; fp32 exp is range-safe here),
// fp32 stored weights; plain accumulate loop.
__global__ __launch_bounds__(256) void aggregate1(const float* __restrict__ b1) {
    int node = blockIdx.x * 8 + (threadIdx.x >> 5);
    if (node >= NN) return;
    int lane = threadIdx.x & 31;
    int beg = g_rowptr[node], end = g_rowptr[node + 1];
    float4 ad = *(const float4*)(g_adst1 + node * 4);

    float s0 = 0.f, s1 = 0.f, s2 = 0.f, s3 = 0.f;
    for (int e = beg + lane; e < end; e += 32) {
        int s = g_csr[e];
        float4 as = *(const float4*)(g_asrc1 + s * 4);
        float4 w;
        w.x = expf(lrelu(as.x + ad.x));
        w.y = expf(lrelu(as.y + ad.y));
        w.z = expf(lrelu(as.z + ad.z));
        w.w = expf(lrelu(as.w + ad.w));
        s0 += w.x; s1 += w.y; s2 += w.z; s3 += w.w;
        *(float4*)&g_ewf[(size_t)e * 4] = w;
    }
    s0 = warpSum(s0); s1 = warpSum(s1); s2 = warpSum(s2); s3 = warpSum(s3);
    float i0 = 1.f / (s0 + 1e-16f), i1 = 1.f / (s1 + 1e-16f);
    float i2 = 1.f / (s2 + 1e-16f), i3 = 1.f / (s3 + 1e-16f);

    int head = lane >> 3;
    float ih = head < 2 ? (head == 0 ? i0 : i1) : (head == 2 ? i2 : i3);

    float acc[8];
    #pragma unroll
    for (int k = 0; k < 8; k++) acc[k] = 0.f;

    const size_t loff = (size_t)lane * 8;
    __syncwarp();
    for (int e = beg; e < end; ++e) {
        int s = g_csr[e];
        float4 w4 = *(const float4*)&g_ewf[(size_t)e * 4];   // broadcast
        float w = (head < 2 ? (head == 0 ? w4.x : w4.y)
                            : (head == 2 ? w4.z : w4.w)) * ih;
        uint4 raw = *(const uint4*)(g_h1h + (size_t)s * 256 + loff);
        const __half2* hp = (const __half2*)&raw;
        #pragma unroll
        for (int q = 0; q < 4; q++) {
            float2 f = __half22float2(hp[q]);
            acc[q * 2]     = fmaf(w, f.x, acc[q * 2]);
            acc[q * 2 + 1] = fmaf(w, f.y, acc[q * 2 + 1]);
        }
    }
    const float* bb = b1 + lane * 8;
    __half2 o[4];
    #pragma unroll
    for (int q = 0; q < 4; q++) {
        float r0 = acc[q * 2]     + bb[q * 2];
        float r1 = acc[q * 2 + 1] + bb[q * 2 + 1];
        r0 = r0 > 0.f ? r0 : (expf(r0) - 1.f);
        r1 = r1 > 0.f ? r1 : (expf(r1) - 1.f);
        o[q] = __floats2half2_rn(r0, r1);
    }
    *(uint4*)(g_e1h + (size_t)node * 256 + loff) = *(const uint4*)o;
}

// ---------------- layer-2 aggregation: single stats pass, plain loop ------
__global__ __launch_bounds__(256) void aggregate2(const float* __restrict__ b2) {
    int node = blockIdx.x * 8 + (threadIdx.x >> 5);
    if (node >= NN) return;
    int lane = threadIdx.x & 31;
    int beg = g_rowptr[node], end = g_rowptr[node + 1];
    float adv = g_adst2[node];

    float sm = 0.f;
    for (int e = beg + lane; e < end; e += 32) {
        float w = expf(lrelu(g_asrc2[g_csr[e]] + adv));
        sm += w;
        g_ewf[e] = w;
    }
    sm = warpSum(sm);
    float inv = 1.f / (sm + 1e-16f);

    float a0 = 0.f, a1 = 0.f;
    const size_t loff = (size_t)lane * 2;
    __syncwarp();
    for (int e = beg; e < end; ++e) {
        int s = g_csr[e];
        float w = g_ewf[e] * inv;   // broadcast
        float2 v = __half22float2(*(const __half2*)(g_h2h + (size_t)s * 64 + loff));
        a0 = fmaf(w, v.x, a0);
        a1 = fmaf(w, v.y, a1);
    }
    *(__half2*)(g_o2h + (size_t)node * 64 + lane * 2) =
        __floats2half2_rn(a0 + b2[lane * 2], a1 + b2[lane * 2 + 1]);
}

// ---------------- fused mean-pool + MLP (last block does the head) --------
__device__ __forceinline__ int lower_bound_i(const int* b, int n, int v) {
    int lo = 0, hi = n;
    while (lo < hi) {
        int mid = (lo + hi) >> 1;
        if (b[mid] < v) lo = mid + 1; else hi = mid;
    }
    return lo;
}
__global__ void pool_mlp(const int* __restrict__ batch,
                         const float* __restrict__ W3, const float* __restrict__ b3,
                         const float* __restrict__ W4, const float* __restrict__ b4,
                         float* __restrict__ out) {
    __shared__ float part[256];
    __shared__ int sb, se;
    __shared__ bool isLast;
    int g = blockIdx.x;
    if (threadIdx.x == 0) {
        sb = lower_bound_i(batch, NN, g);
        se = lower_bound_i(batch, NN, g + 1);
    }
    __syncthreads();
    int c = threadIdx.x & 63, q = threadIdx.x >> 6;
    float s = 0.f;
    for (int i = sb + q; i < se; i += 4)
        s += __half2float(g_o2h[(size_t)i * 64 + c]);
    part[threadIdx.x] = s;
    __syncthreads();
    if (q == 0) {
        float t = part[c] + part[c + 64] + part[c + 128] + part[c + 192];
        float cnt = (float)(se - sb);
        g_emb[g * 64 + c] = t / fmaxf(cnt, 1.f);
    }
    // --- last block runs the MLP head ---
    __threadfence();
    if (threadIdx.x == 0) {
        int prev = atomicAdd(&g_poolctr, 1);
        isLast = (prev == GG - 1);
        if (isLast) g_poolctr = 0;  // reset for deterministic graph replay
    }
    __syncthreads();
    if (!isLast) return;

    __shared__ float w3[64 * 32], w4s[64], bb3[32], bb4[2];
    int t = threadIdx.x;
    for (int i = t; i < 2048; i += 256) w3[i] = W3[i];
    if (t < 64) w4s[t] = W4[t];
    if (t < 32) bb3[t] = b3[t];
    if (t < 2) bb4[t] = b4[t];
    __syncthreads();
    if (t < 64) {
        float e[64];
        #pragma unroll
        for (int k = 0; k < 64; k++) e[k] = g_emb[t * 64 + k];
        float l0 = bb4[0], l1 = bb4[1];
        #pragma unroll 4
        for (int j = 0; j < 32; j++) {
            float z = bb3[j];
            #pragma unroll
            for (int k = 0; k < 64; k++) z = fmaf(e[k], w3[k * 32 + j], z);
            z = fmaxf(z, 0.f);
            l0 = fmaf(z, w4s[j * 2], l0);
            l1 = fmaf(z, w4s[j * 2 + 1], l1);
        }
        out[t * 2] = l0;
        out[t * 2 + 1] = l1;
    }
}

// ---------------- launch ----------------
extern "C" void kernel_launch(void* const* d_in, const int* in_sizes, int n_in,
                              void* d_out, int out_size) {
    const float* x = (const float*)d_in[0];
    const int* ei = (const int*)d_in[1];
    const int* batch = (const int*)d_in[2];
    const float* W1 = (const float*)d_in[3];
    const float* as1 = (const float*)d_in[4];
    const float* ad1 = (const float*)d_in[5];
    const float* b1 = (const float*)d_in[6];
    const float* W2 = (const float*)d_in[7];
    const float* as2 = (const float*)d_in[8];
    const float* ad2 = (const float*)d_in[9];
    const float* b2 = (const float*)d_in[10];
    const float* W3 = (const float*)d_in[11];
    const float* b3 = (const float*)d_in[12];
    const float* W4 = (const float*)d_in[13];
    const float* b4 = (const float*)d_in[14];
    float* out = (float*)d_out;

    const int* e_src = ei;
    const int* e_dst = ei + EE;

    void* p;
    cudaGetSymbolAddress(&p, g_h1h);  __half* h1 = (__half*)p;
    cudaGetSymbolAddress(&p, g_e1h);  __half* e1 = (__half*)p;
    cudaGetSymbolAddress(&p, g_h2h);  __half* h2 = (__half*)p;
    cudaGetSymbolAddress(&p, g_w1h);  __half* w1h = (__half*)p;
    cudaGetSymbolAddress(&p, g_w2h);  __half* w2h = (__half*)p;

    static cudaStream_t sB = nullptr;
    static cudaEvent_t evRoot = nullptr, evB = nullptr;
    if (!sB) {
        cudaStreamCreateWithFlags(&sB, cudaStreamNonBlocking);
        cudaEventCreateWithFlags(&evRoot, cudaEventDisableTiming);
        cudaEventCreateWithFlags(&evB, cudaEventDisableTiming);
    }

    const int agg_blocks = NN / 8;  // 12500, exact

    // ---- fork: CSR build on side stream, GEMM1(+att1) on main ----
    cudaEventRecord(evRoot, 0);
    cudaStreamWaitEvent(sB, evRoot, 0);

    prepW<<<256, 256>>>(W1, W2);
    init_cnt<<<(NN + 255) / 256, 256, 0, sB>>>();
    count_edges<<<(EE + 255) / 256, 256, 0, sB>>>(e_dst);
    gemm_h<128, false, true, false><<<dim3(2, 782), 256>>>(x, w1h, h1, NN, 256, 256, as1, ad1);
    scan1<<<NBLK_SCAN, SCAN_BLK, 0, sB>>>();
    scan3<<<(NN + 255) / 256, 256, 0, sB>>>();
    scatter_edges<<<(EE + NN + 255) / 256, 256, 0, sB>>>(e_src, e_dst);
    cudaEventRecord(evB, sB);
    cudaStreamWaitEvent(0, evB, 0);

    aggregate1<<<agg_blocks, 256>>>(b1);
    // GEMM2 with fused attn2 epilogue
    gemm_h<64, true, false, true><<<dim3(1, 782), 256>>>(e1, w2h, h2, NN, 256, 64, as2, ad2);
    aggregate2<<<agg_blocks, 256>>>(b2);
    // fused mean pool + MLP head
    pool_mlp<<<GG, 256>>>(batch, W3, b3, W4, b4, out);
}